// round 5
// baseline (speedup 1.0000x reference)
#include <cuda_runtime.h>
#include <cuda_fp16.h>

#define N_SAMP   1024
#define N_COL    128
#define TILE     128
#define HTILE    64             // j handled in half2 pairs
#define N_TP     36             // tile-pairs with ti <= tj
#define N_BLOCKS (N_TP * N_COL) // 4608

__constant__ unsigned char c_ti[N_TP] = {
    0,0,0,0,0,0,0,0,
    1,1,1,1,1,1,1,
    2,2,2,2,2,2,
    3,3,3,3,3,
    4,4,4,4,
    5,5,5,
    6,6,
    7
};
__constant__ unsigned char c_tj[N_TP] = {
    0,1,2,3,4,5,6,7,
    1,2,3,4,5,6,7,
    2,3,4,5,6,7,
    3,4,5,6,7,
    4,5,6,7,
    5,6,7,
    6,7,
    7
};

// Order-independent integer accumulation -> bit-deterministic across replays.
__device__ long long    g_sum;
__device__ unsigned int g_count;

#define SUM_SCALE 268435456.0    // 2^28

__device__ __forceinline__ unsigned tanh2_fast(unsigned x) {
    unsigned r;
    asm("tanh.approx.f16x2 %0, %1;" : "=r"(r) : "r"(x));
    return r;
}

// one fused step: acc2 += tanh(pi2 - pj2) ^ signbits(li2 - lj2)
__device__ __forceinline__ void tau_step(
    const uint2 e, const __half2 pi2, const __half2 li2, __half2& acc2)
{
    __half2 pj2 = *reinterpret_cast<const __half2*>(&e.x);
    __half2 lj2 = *reinterpret_cast<const __half2*>(&e.y);
    __half2 d2  = __hsub2(pi2, pj2);
    __half2 ld2 = __hsub2(li2, lj2);
    unsigned t  = tanh2_fast(*reinterpret_cast<unsigned*>(&d2));
    // t * sign(ld) per lane via sign-bit xor (single LOP3).
    unsigned st = t ^ (*reinterpret_cast<unsigned*>(&ld2) & 0x80008000u);
    acc2 = __hadd2(acc2, *reinterpret_cast<__half2*>(&st));
}

__global__ __launch_bounds__(TILE) void tau_fused_kernel(
    const float* __restrict__ pred, const float* __restrict__ y,
    float* __restrict__ out)
{
    const int tp  = blockIdx.x;   // 0..35
    const int col = blockIdx.y;   // 0..127
    const int tid = threadIdx.x;  // 0..127

    const int ti = c_ti[tp];
    const int tj = c_tj[tp];

    const float* pc = pred + col * N_SAMP;
    const float* lc = y    + col * N_SAMP;

    // this thread's i-row values, broadcast into both f16 lanes
    const float pif = pc[ti * TILE + tid];
    const float lif = lc[ti * TILE + tid];
    const __half2 pi2 = __half2half2(__float2half_rn(pif));
    const __half2 li2 = __half2half2(__float2half_rn(lif));

    // j-tile in shared: 64 entries of {half2(p[2k],p[2k+1]), half2(l[2k],l[2k+1])}
    __shared__ uint2 sj[HTILE];
    if (tid < HTILE) {
        float2 pv = reinterpret_cast<const float2*>(pc + tj * TILE)[tid];
        float2 lv = reinterpret_cast<const float2*>(lc + tj * TILE)[tid];
        __half2 p2 = __floats2half2_rn(pv.x, pv.y);
        __half2 l2 = __floats2half2_rn(lv.x, lv.y);
        sj[tid] = make_uint2(*reinterpret_cast<unsigned*>(&p2),
                             *reinterpret_cast<unsigned*>(&l2));
    }
    __syncthreads();

    float acc = 0.0f;

    if (ti != tj) {
        // full 64 half2-steps, flush f16 accumulator every 16
        #pragma unroll
        for (int c = 0; c < 4; ++c) {
            __half2 acc2 = __float2half2_rn(0.0f);
            #pragma unroll
            for (int k = 0; k < 16; ++k)
                tau_step(sj[c * 16 + k], pi2, li2, acc2);
            acc += __low2float(acc2) + __high2float(acc2);
        }
    } else {
        // diagonal tile: pairs j >= tid only (j == tid contributes exactly 0:
        // d == 0 -> tanh == +-0, sign xor keeps it zero)
        const int k0 = (tid + 1) >> 1;   // first half2 index containing only j >= tid
        __half2 acc2 = __float2half2_rn(0.0f);
        for (int k = k0; k < HTILE; ++k)
            tau_step(sj[k], pi2, li2, acc2);
        acc += __low2float(acc2) + __high2float(acc2);
    }

    // every tile-pair carries weight 2 (both orderings; tanh is odd)
    acc *= 2.0f;

    // block reduction
    #pragma unroll
    for (int off = 16; off > 0; off >>= 1)
        acc += __shfl_down_sync(0xffffffffu, acc, off);

    __shared__ float warp_sums[TILE / 32];
    if ((tid & 31) == 0) warp_sums[tid >> 5] = acc;
    __syncthreads();

    if (tid == 0) {
        float total = warp_sums[0] + warp_sums[1] + warp_sums[2] + warp_sums[3];

        long long q = llrint((double)total * SUM_SCALE);
        atomicAdd((unsigned long long*)&g_sum, (unsigned long long)q);
        __threadfence();

        unsigned prev = atomicAdd(&g_count, 1u);
        if (prev == (unsigned)(N_BLOCKS - 1)) {
            __threadfence();
            long long s = *((volatile long long*)&g_sum);
            const double norm = (double)N_COL * (double)N_SAMP * (double)(N_SAMP - 1);
            out[0] = (float)(1.0 - ((double)s / SUM_SCALE) / norm);
            *((volatile long long*)&g_sum)      = 0;
            *((volatile unsigned int*)&g_count) = 0u;
            __threadfence();
        }
    }
}

extern "C" void kernel_launch(void* const* d_in, const int* in_sizes, int n_in,
                              void* d_out, int out_size)
{
    const float* pred = (const float*)d_in[0];
    const float* y    = (const float*)d_in[1];
    float* out        = (float*)d_out;

    dim3 grid(N_TP, N_COL);
    tau_fused_kernel<<<grid, TILE>>>(pred, y, out);
}